// round 9
// baseline (speedup 1.0000x reference)
#include <cuda_runtime.h>
#include <cstdint>

#define B_ 4
#define H_ 16
#define T_ 2048
#define K_ 64
#define CH_ 128
#define N_ 16
#define BH_ (B_*H_)
#define OUT_ELEMS (B_*H_*T_*K_)
#define LOGMIN (-5.2983174324035645f)

// ---- scratch ----
__device__ float g_rwi[B_*H_*T_*K_];      // r * exp(cum_prev)  (tf32-rounded)
__device__ float g_wkv[BH_*N_*K_*K_];
__device__ float g_wse[BH_*N_*K_];

// ---- phase1 smem layout (float offsets) ----
#define O_RW    0        // 128 x 64, stride 68 (8704); after MMA1 reused as partial buf
#define O_CUM   8704     // 128 x 64, stride 64 (8192)
#define O_KK    16896    // 128 x 64, stride 76 (9728)
#define O_V     26624    // 128 x 64, stride 72 (9216)
#define O_U     35840
#define O_DIAG  35904    // 128
#define O_EWS   36032    // 64
#define O_SEG   36096    // 8 x 64
#define SMEM1_FLOATS 36608
#define SMEM1_BYTES  (SMEM1_FLOATS*4)

__device__ __forceinline__ float f2tf(float x) {
    uint32_t r;
    asm("cvt.rna.tf32.f32 %0, %1;" : "=r"(r) : "f"(x));
    return __uint_as_float(r);
}
__device__ __forceinline__ void mma1688(float* c, uint32_t a0, uint32_t a1, uint32_t a2, uint32_t a3,
                                        uint32_t b0, uint32_t b1) {
    asm volatile("mma.sync.aligned.m16n8k8.row.col.f32.tf32.tf32.f32 "
                 "{%0,%1,%2,%3},{%4,%5,%6,%7},{%8,%9},{%0,%1,%2,%3};"
                 : "+f"(c[0]), "+f"(c[1]), "+f"(c[2]), "+f"(c[3])
                 : "r"(a0), "r"(a1), "r"(a2), "r"(a3), "r"(b0), "r"(b1));
}
#define FB(x) __float_as_uint(x)

// ======================= phase 1 (round-6 best version) =======================
__global__ void __launch_bounds__(512)
rwkv_phase1(const float* __restrict__ r, const float* __restrict__ k,
            const float* __restrict__ v, const float* __restrict__ w,
            const float* __restrict__ u, float* __restrict__ out)
{
    extern __shared__ float sm[];
    const int tid = threadIdx.x;
    const int wid = tid >> 5, lid = tid & 31;
    const int ly = lid >> 2, lx = lid & 3;
    const int bhn = blockIdx.x;
    const int bh = bhn >> 4, n = bhn & 15;
    const int h = bh & (H_ - 1);
    const int base = bh * (T_ * K_) + n * (CH_ * K_);

    float4 pr[4], pk[4];
    {
        const float4* r4g = (const float4*)(r + base);
        const float4* k4g = (const float4*)(k + base);
        #pragma unroll
        for (int it = 0; it < 4; ++it) {
            pr[it] = r4g[tid + it * 512];
            pk[it] = k4g[tid + it * 512];
        }
    }

    {
        const float4* w4 = (const float4*)(w + base);
        const float4* v4 = (const float4*)(v + base);
        #pragma unroll
        for (int it = 0; it < 4; ++it) {
            int f4 = tid + it * 512;
            int t = f4 >> 4, k0 = (f4 & 15) * 4;
            float4 ww = w4[f4];
            ww.x = fmaxf(ww.x, LOGMIN); ww.y = fmaxf(ww.y, LOGMIN);
            ww.z = fmaxf(ww.z, LOGMIN); ww.w = fmaxf(ww.w, LOGMIN);
            *(float4*)&sm[O_CUM + t * 64 + k0] = ww;
            float4 vv = v4[f4];
            vv.x = f2tf(vv.x); vv.y = f2tf(vv.y); vv.z = f2tf(vv.z); vv.w = f2tf(vv.w);
            *(float4*)&sm[O_V + t * 72 + k0] = vv;
        }
        if (tid < 64) sm[O_U + tid] = u[h * 64 + tid];
    }
    __syncthreads();

    {
        int kq = tid & 63, seg = tid >> 6;
        float run = 0.f;
        #pragma unroll
        for (int tt = 0; tt < 16; ++tt) {
            int idx = (seg * 16 + tt) * 64 + kq;
            run += sm[O_CUM + idx];
            sm[O_CUM + idx] = run;
        }
        sm[O_SEG + seg * 64 + kq] = run;
    }
    __syncthreads();

    {
        int kq = tid & 63, seg = tid >> 6;
        if (seg > 0) {
            float pre = 0.f;
            #pragma unroll
            for (int s = 0; s < 7; ++s)
                if (s < seg) pre += sm[O_SEG + s * 64 + kq];
            #pragma unroll
            for (int tt = 0; tt < 16; ++tt) sm[O_CUM + (seg * 16 + tt) * 64 + kq] += pre;
        } else {
            float ws = 0.f;
            #pragma unroll
            for (int s = 0; s < 8; ++s) ws += sm[O_SEG + s * 64 + kq];
            float ews = __expf(ws);
            sm[O_EWS + kq] = ews;
            g_wse[(bh * N_ + n) * K_ + kq] = ews;
        }
    }
    __syncthreads();

    {
        #pragma unroll
        for (int it = 0; it < 4; ++it) {
            int f4 = tid + it * 512;
            int t = f4 >> 4, k0 = (f4 & 15) * 4;
            float4 rv = pr[it];
            float4 kv = pk[it];
            float4 c4 = *(const float4*)&sm[O_CUM + t * 64 + k0];
            float4 cp4 = (t > 0) ? *(const float4*)&sm[O_CUM + (t - 1) * 64 + k0]
                                 : make_float4(0.f, 0.f, 0.f, 0.f);
            float4 uu = *(const float4*)&sm[O_U + k0];
            float re[4] = {rv.x, rv.y, rv.z, rv.w};
            float ke[4] = {kv.x, kv.y, kv.z, kv.w};
            float ce[4] = {c4.x, c4.y, c4.z, c4.w};
            float cpe[4] = {cp4.x, cp4.y, cp4.z, cp4.w};
            float ue[4] = {uu.x, uu.y, uu.z, uu.w};
            float rwv[4], kkv[4];
            float dpart = 0.f;
            #pragma unroll
            for (int e = 0; e < 4; ++e) {
                rwv[e] = f2tf(re[e] * __expf(cpe[e]));
                kkv[e] = f2tf(ke[e] * __expf(-ce[e]));
                dpart += re[e] * ue[e] * ke[e];
            }
            *(float4*)&sm[O_RW + t * 68 + k0] = make_float4(rwv[0], rwv[1], rwv[2], rwv[3]);
            *(float4*)&sm[O_KK + t * 76 + k0] = make_float4(kkv[0], kkv[1], kkv[2], kkv[3]);
            *(float4*)&g_rwi[base + f4 * 4]   = make_float4(rwv[0], rwv[1], rwv[2], rwv[3]);
            float dv = dpart;
            #pragma unroll
            for (int s = 1; s < 16; s <<= 1) dv += __shfl_xor_sync(0xffffffffu, dv, s, 16);
            if ((tid & 15) == 0) sm[O_DIAG + t] = dv;
        }
    }
    __syncthreads();

    const int jh = wid >> 3;
    const int widL = wid & 7;
    const int blk = (widL < 4) ? widL : 11 - widL;
    const int i0 = blk * 16;
    int ntmax = (i0 + 16 - jh * 64) >> 3;
    ntmax = ntmax < 0 ? 0 : (ntmax > 8 ? 8 : ntmax);

    float c1[8][4];
    #pragma unroll
    for (int nt = 0; nt < 8; ++nt)
        #pragma unroll
        for (int e = 0; e < 4; ++e) c1[nt][e] = 0.f;

    #pragma unroll
    for (int ks = 0; ks < 8; ++ks) {
        int k0 = ks * 8;
        const float* ar = &sm[O_RW + (i0 + ly) * 68 + k0 + lx];
        uint32_t a0 = FB(ar[0]), a1 = FB(ar[8 * 68]), a2 = FB(ar[4]), a3 = FB(ar[8 * 68 + 4]);
        #pragma unroll
        for (int nt = 0; nt < 8; ++nt) {
            if (nt < ntmax) {
                const float* br = &sm[O_KK + (jh * 64 + nt * 8 + ly) * 76 + k0 + lx];
                mma1688(c1[nt], a0, a1, a2, a3, FB(br[0]), FB(br[4]));
            }
        }
    }

    {
        const int i0k = (wid & 3) * 16, j0c = (wid >> 2) * 16;
        float c3[2][4];
        #pragma unroll
        for (int nt = 0; nt < 2; ++nt)
            #pragma unroll
            for (int e = 0; e < 4; ++e) c3[nt][e] = 0.f;
        #pragma unroll
        for (int ks = 0; ks < 16; ++ks) {
            int k0 = ks * 8;
            const float* ac = &sm[O_KK + (k0 + lx) * 76 + i0k + ly];
            uint32_t a0 = FB(ac[0]), a1 = FB(ac[8]), a2 = FB(ac[4 * 76]), a3 = FB(ac[4 * 76 + 8]);
            #pragma unroll
            for (int nt = 0; nt < 2; ++nt) {
                const float* br = &sm[O_V + (k0 + lx) * 72 + j0c + nt * 8 + ly];
                mma1688(c3[nt], a0, a1, a2, a3, FB(br[0]), FB(br[4 * 72]));
            }
        }
        int wb = bhn * (K_ * K_);
        int il = i0k + ly, ih = il + 8;
        float sl = sm[O_EWS + il], sh = sm[O_EWS + ih];
        #pragma unroll
        for (int nt = 0; nt < 2; ++nt) {
            int jb = j0c + nt * 8 + 2 * lx;
            *(float2*)&g_wkv[wb + il * 64 + jb] = make_float2(c3[nt][0] * sl, c3[nt][1] * sl);
            *(float2*)&g_wkv[wb + ih * 64 + jb] = make_float2(c3[nt][2] * sh, c3[nt][3] * sh);
        }
    }
    __syncthreads();

    float c2[8][4];
    #pragma unroll
    for (int nt = 0; nt < 8; ++nt)
        #pragma unroll
        for (int e = 0; e < 4; ++e) c2[nt][e] = 0.f;

    {
        const int il = i0 + ly, ih = il + 8;
        const int l1 = ly * 4 + (lx >> 1);
        const int l2 = l1 + 2;
        const bool odd = lx & 1;
        #pragma unroll
        for (int nt = 0; nt < 8; ++nt) {
            if (nt < ntmax) {
                int jc = jh * 64 + nt * 8;
                int jcg = jc + 2 * lx;
                float m0 = (jcg     < il) ? f2tf(c1[nt][0]) : 0.f;
                float m1 = (jcg + 1 < il) ? f2tf(c1[nt][1]) : 0.f;
                float m2 = (jcg     < ih) ? f2tf(c1[nt][2]) : 0.f;
                float m3 = (jcg + 1 < ih) ? f2tf(c1[nt][3]) : 0.f;
                float t00 = __shfl_sync(0xffffffffu, m0, l1);
                float t01 = __shfl_sync(0xffffffffu, m1, l1);
                float t20 = __shfl_sync(0xffffffffu, m0, l2);
                float t21 = __shfl_sync(0xffffffffu, m1, l2);
                float t10 = __shfl_sync(0xffffffffu, m2, l1);
                float t11 = __shfl_sync(0xffffffffu, m3, l1);
                float t30 = __shfl_sync(0xffffffffu, m2, l2);
                float t31 = __shfl_sync(0xffffffffu, m3, l2);
                uint32_t a0 = FB(odd ? t01 : t00);
                uint32_t a2 = FB(odd ? t21 : t20);
                uint32_t a1 = FB(odd ? t11 : t10);
                uint32_t a3 = FB(odd ? t31 : t30);
                #pragma unroll
                for (int no = 0; no < 8; ++no) {
                    const float* br = &sm[O_V + (jc + lx) * 72 + no * 8 + ly];
                    mma1688(c2[no], a0, a1, a2, a3, FB(br[0]), FB(br[4 * 72]));
                }
            }
        }
    }

    if (jh == 1 && ntmax > 0) {
        float* pb = &sm[O_RW + (blk - 4) * 1088];
        int jb = 2 * lx;
        #pragma unroll
        for (int nt = 0; nt < 8; ++nt) {
            *(float2*)&pb[ly * 68 + nt * 8 + jb]       = make_float2(c2[nt][0], c2[nt][1]);
            *(float2*)&pb[(ly + 8) * 68 + nt * 8 + jb] = make_float2(c2[nt][2], c2[nt][3]);
        }
    }
    __syncthreads();

    if (jh == 0) {
        const int il = i0 + ly, ih = il + 8;
        const float dgl = sm[O_DIAG + il], dgh = sm[O_DIAG + ih];
        const bool haveP = (blk >= 4);
        const float* pb = &sm[O_RW + (blk - 4) * 1088];
        #pragma unroll
        for (int nt = 0; nt < 8; ++nt) {
            int jb = nt * 8 + 2 * lx;
            float2 pl = make_float2(0.f, 0.f), ph = make_float2(0.f, 0.f);
            if (haveP) {
                pl = *(const float2*)&pb[ly * 68 + jb];
                ph = *(const float2*)&pb[(ly + 8) * 68 + jb];
            }
            float2 vl = *(const float2*)&sm[O_V + il * 72 + jb];
            float2 vh = *(const float2*)&sm[O_V + ih * 72 + jb];
            float o0 = c2[nt][0] + pl.x + dgl * vl.x;
            float o1 = c2[nt][1] + pl.y + dgl * vl.y;
            float o2 = c2[nt][2] + ph.x + dgh * vh.x;
            float o3 = c2[nt][3] + ph.y + dgh * vh.y;
            *(float2*)&out[base + il * 64 + jb] = make_float2(o0, o1);
            *(float2*)&out[base + ih * 64 + jb] = make_float2(o2, o3);
        }
    }
}

// ============ fused scan + inter-chunk contribution (v2: row+col split) ============
// grid: bh(64) x row-half(2) x col-quarter(4) = 512 blocks.
// Each block: 64 out rows x 16 state cols, state slice scanned redundantly per row-half.
#define F_RW0  0         // 64 x 64, stride 68 (4352)
#define F_RW1  4352
#define F_ST0  8704      // 64 x 16, stride 24 (1536)
#define F_ST1  10240
#define FUSED_FLOATS 11776
#define FUSED_BYTES  (FUSED_FLOATS*4)

__global__ void __launch_bounds__(256)
rwkv_scan_inter(const float* __restrict__ state0, float* __restrict__ out,
                float* __restrict__ outF)
{
    extern __shared__ float sm[];
    const int tid = threadIdx.x;
    const int wid = tid >> 5, lid = tid & 31;
    const int ly = lid >> 2, lx = lid & 3;
    const int bidx = blockIdx.x;
    const int bh = bidx >> 3;
    const int rs = (bidx >> 2) & 1;       // row half: rows rs*64 .. rs*64+63
    const int cs = bidx & 3;              // col quarter
    const int j0c = cs * 16;
    const int r0 = rs * 64;
    const int base_bh = bh * (T_ * K_);

    // state ownership: thread -> state row kq, cols j0c+jq..+3 (exact fp32 regs)
    const int kq = tid >> 2;
    const int jq = (tid & 3) * 4;
    float4 st = *(const float4*)&state0[bh * (K_ * K_) + kq * 64 + j0c + jq];

    // preload chunk-0 rw rows [r0, r0+64) and state slice
    {
        const float4* rw4 = (const float4*)(g_rwi + base_bh + r0 * 64);
        #pragma unroll
        for (int it = 0; it < 4; ++it) {
            int f4 = tid + it * 256;
            int t = f4 >> 4, k0 = (f4 & 15) * 4;
            *(float4*)&sm[F_RW0 + t * 68 + k0] = rw4[f4];
        }
        float4 sr = make_float4(f2tf(st.x), f2tf(st.y), f2tf(st.z), f2tf(st.w));
        *(float4*)&sm[F_ST0 + kq * 24 + jq] = sr;
    }
    __syncthreads();

    // warp tile: 16 rows x 8 cols
    const int i0 = (wid & 3) * 16;        // local row block
    const int jn = (wid >> 2) * 8;        // col offset within 16-col slice

    for (int n = 0; n < N_; ++n) {
        const int cur  = (n & 1) ? F_RW1 : F_RW0;
        const int curS = (n & 1) ? F_ST1 : F_ST0;
        const int nxt  = (n & 1) ? F_RW0 : F_RW1;
        const int nxtS = (n & 1) ? F_ST0 : F_ST1;

        // prefetch next rw chunk (regs)
        float4 pf[4];
        {
            int np = (n < 15) ? n + 1 : 15;
            const float4* rw4 = (const float4*)(g_rwi + base_bh + np * (CH_ * K_) + r0 * 64);
            #pragma unroll
            for (int it = 0; it < 4; ++it) pf[it] = rw4[tid + it * 256];
        }
        // prefetch wkv + ews for state update
        const int cb = bh * N_ + n;
        float4 wkvv = *(const float4*)&g_wkv[cb * (K_ * K_) + kq * 64 + j0c + jq];
        float ews = __ldg(&g_wse[cb * K_ + kq]);

        // prefetch out tile (RMW load overlaps MMAs)
        float* ob = out + base_bh + n * (CH_ * K_) + r0 * 64;
        const int il = i0 + ly, ih = il + 8;
        const int jb = j0c + jn + 2 * lx;
        float2 o_l = *(const float2*)&ob[il * 64 + jb];
        float2 o_h = *(const float2*)&ob[ih * 64 + jb];

        // MMA: 16x8 tile += rw(16x64) @ state(64x8)
        float c[4] = {0.f, 0.f, 0.f, 0.f};
        #pragma unroll
        for (int ks = 0; ks < 8; ++ks) {
            int k0 = ks * 8;
            const float* ar = &sm[cur + (i0 + ly) * 68 + k0 + lx];
            const float* br = &sm[curS + (k0 + lx) * 24 + jn + ly];
            mma1688(c, FB(ar[0]), FB(ar[8 * 68]), FB(ar[4]), FB(ar[8 * 68 + 4]),
                    FB(br[0]), FB(br[4 * 24]));
        }
        o_l.x += c[0]; o_l.y += c[1];
        o_h.x += c[2]; o_h.y += c[3];
        *(float2*)&ob[il * 64 + jb] = o_l;
        *(float2*)&ob[ih * 64 + jb] = o_h;

        // state update (exact)
        st.x = fmaf(st.x, ews, wkvv.x);
        st.y = fmaf(st.y, ews, wkvv.y);
        st.z = fmaf(st.z, ews, wkvv.z);
        st.w = fmaf(st.w, ews, wkvv.w);

        if (n < 15) {
            #pragma unroll
            for (int it = 0; it < 4; ++it) {
                int f4 = tid + it * 256;
                int t = f4 >> 4, k0 = (f4 & 15) * 4;
                *(float4*)&sm[nxt + t * 68 + k0] = pf[it];
            }
            float4 sr = make_float4(f2tf(st.x), f2tf(st.y), f2tf(st.z), f2tf(st.w));
            *(float4*)&sm[nxtS + kq * 24 + jq] = sr;
            __syncthreads();
        }
    }

    if (rs == 0)
        *(float4*)&outF[bh * (K_ * K_) + kq * 64 + j0c + jq] = st;
}

extern "C" void kernel_launch(void* const* d_in, const int* in_sizes, int n_in,
                              void* d_out, int out_size)
{
    (void)in_sizes; (void)n_in; (void)out_size;
    const float* r  = (const float*)d_in[0];
    const float* k  = (const float*)d_in[1];
    const float* v  = (const float*)d_in[2];
    const float* w  = (const float*)d_in[3];
    const float* u  = (const float*)d_in[4];
    const float* s0 = (const float*)d_in[5];
    float* out  = (float*)d_out;
    float* outF = out + OUT_ELEMS;

    cudaFuncSetAttribute(rwkv_phase1, cudaFuncAttributeMaxDynamicSharedMemorySize, SMEM1_BYTES);
    cudaFuncSetAttribute(rwkv_scan_inter, cudaFuncAttributeMaxDynamicSharedMemorySize, FUSED_BYTES);

    rwkv_phase1<<<BH_ * N_, 512, SMEM1_BYTES>>>(r, k, v, w, u, out);
    rwkv_scan_inter<<<BH_ * 8, 256, FUSED_BYTES>>>(s0, out, outF);
}

// round 10
// speedup vs baseline: 1.0169x; 1.0169x over previous
#include <cuda_runtime.h>
#include <cstdint>

#define B_ 4
#define H_ 16
#define T_ 2048
#define K_ 64
#define CH_ 128
#define N_ 16
#define BH_ (B_*H_)
#define OUT_ELEMS (B_*H_*T_*K_)
#define LOGMIN (-5.2983174324035645f)

// ---- scratch ----
__device__ float g_rwi[B_*H_*T_*K_];      // r * exp(cum_prev)  (tf32-rounded)
__device__ float g_wkv[BH_*N_*K_*K_];
__device__ float g_wse[BH_*N_*K_];

// ---- phase1 smem layout (float offsets) ----
#define O_RW    0        // 128 x 64, stride 68 (8704); after MMA1 reused as partial buf
#define O_CUM   8704     // 128 x 64, stride 64 (8192)
#define O_KK    16896    // 128 x 64, stride 76 (9728)
#define O_V     26624    // 128 x 64, stride 72 (9216)
#define O_U     35840
#define O_DIAG  35904    // 128
#define O_EWS   36032    // 64
#define O_SEG   36096    // 8 x 64
#define SMEM1_FLOATS 36608
#define SMEM1_BYTES  (SMEM1_FLOATS*4)

__device__ __forceinline__ float f2tf(float x) {
    uint32_t r;
    asm("cvt.rna.tf32.f32 %0, %1;" : "=r"(r) : "f"(x));
    return __uint_as_float(r);
}
__device__ __forceinline__ void mma1688(float* c, uint32_t a0, uint32_t a1, uint32_t a2, uint32_t a3,
                                        uint32_t b0, uint32_t b1) {
    asm volatile("mma.sync.aligned.m16n8k8.row.col.f32.tf32.tf32.f32 "
                 "{%0,%1,%2,%3},{%4,%5,%6,%7},{%8,%9},{%0,%1,%2,%3};"
                 : "+f"(c[0]), "+f"(c[1]), "+f"(c[2]), "+f"(c[3])
                 : "r"(a0), "r"(a1), "r"(a2), "r"(a3), "r"(b0), "r"(b1));
}
#define FB(x) __float_as_uint(x)

__device__ __forceinline__ uint32_t smem_u32(const void* p) {
    uint32_t a;
    asm("{ .reg .u64 t; cvta.to.shared.u64 t, %1; cvt.u32.u64 %0, t; }" : "=r"(a) : "l"(p));
    return a;
}
__device__ __forceinline__ void cp_async16(uint32_t dst, const void* src) {
    asm volatile("cp.async.cg.shared.global [%0], [%1], 16;" :: "r"(dst), "l"(src) : "memory");
}
__device__ __forceinline__ void cp_commit() { asm volatile("cp.async.commit_group;" ::: "memory"); }
__device__ __forceinline__ void cp_wait0()  { asm volatile("cp.async.wait_group 0;" ::: "memory"); }

// ======================= phase 1 (round-6/8 best version) =======================
__global__ void __launch_bounds__(512)
rwkv_phase1(const float* __restrict__ r, const float* __restrict__ k,
            const float* __restrict__ v, const float* __restrict__ w,
            const float* __restrict__ u, float* __restrict__ out)
{
    extern __shared__ float sm[];
    const int tid = threadIdx.x;
    const int wid = tid >> 5, lid = tid & 31;
    const int ly = lid >> 2, lx = lid & 3;
    const int bhn = blockIdx.x;
    const int bh = bhn >> 4, n = bhn & 15;
    const int h = bh & (H_ - 1);
    const int base = bh * (T_ * K_) + n * (CH_ * K_);

    float4 pr[4], pk[4];
    {
        const float4* r4g = (const float4*)(r + base);
        const float4* k4g = (const float4*)(k + base);
        #pragma unroll
        for (int it = 0; it < 4; ++it) {
            pr[it] = r4g[tid + it * 512];
            pk[it] = k4g[tid + it * 512];
        }
    }

    {
        const float4* w4 = (const float4*)(w + base);
        const float4* v4 = (const float4*)(v + base);
        #pragma unroll
        for (int it = 0; it < 4; ++it) {
            int f4 = tid + it * 512;
            int t = f4 >> 4, k0 = (f4 & 15) * 4;
            float4 ww = w4[f4];
            ww.x = fmaxf(ww.x, LOGMIN); ww.y = fmaxf(ww.y, LOGMIN);
            ww.z = fmaxf(ww.z, LOGMIN); ww.w = fmaxf(ww.w, LOGMIN);
            *(float4*)&sm[O_CUM + t * 64 + k0] = ww;
            float4 vv = v4[f4];
            vv.x = f2tf(vv.x); vv.y = f2tf(vv.y); vv.z = f2tf(vv.z); vv.w = f2tf(vv.w);
            *(float4*)&sm[O_V + t * 72 + k0] = vv;
        }
        if (tid < 64) sm[O_U + tid] = u[h * 64 + tid];
    }
    __syncthreads();

    {
        int kq = tid & 63, seg = tid >> 6;
        float run = 0.f;
        #pragma unroll
        for (int tt = 0; tt < 16; ++tt) {
            int idx = (seg * 16 + tt) * 64 + kq;
            run += sm[O_CUM + idx];
            sm[O_CUM + idx] = run;
        }
        sm[O_SEG + seg * 64 + kq] = run;
    }
    __syncthreads();

    {
        int kq = tid & 63, seg = tid >> 6;
        if (seg > 0) {
            float pre = 0.f;
            #pragma unroll
            for (int s = 0; s < 7; ++s)
                if (s < seg) pre += sm[O_SEG + s * 64 + kq];
            #pragma unroll
            for (int tt = 0; tt < 16; ++tt) sm[O_CUM + (seg * 16 + tt) * 64 + kq] += pre;
        } else {
            float ws = 0.f;
            #pragma unroll
            for (int s = 0; s < 8; ++s) ws += sm[O_SEG + s * 64 + kq];
            float ews = __expf(ws);
            sm[O_EWS + kq] = ews;
            g_wse[(bh * N_ + n) * K_ + kq] = ews;
        }
    }
    __syncthreads();

    {
        #pragma unroll
        for (int it = 0; it < 4; ++it) {
            int f4 = tid + it * 512;
            int t = f4 >> 4, k0 = (f4 & 15) * 4;
            float4 rv = pr[it];
            float4 kv = pk[it];
            float4 c4 = *(const float4*)&sm[O_CUM + t * 64 + k0];
            float4 cp4 = (t > 0) ? *(const float4*)&sm[O_CUM + (t - 1) * 64 + k0]
                                 : make_float4(0.f, 0.f, 0.f, 0.f);
            float4 uu = *(const float4*)&sm[O_U + k0];
            float re[4] = {rv.x, rv.y, rv.z, rv.w};
            float ke[4] = {kv.x, kv.y, kv.z, kv.w};
            float ce[4] = {c4.x, c4.y, c4.z, c4.w};
            float cpe[4] = {cp4.x, cp4.y, cp4.z, cp4.w};
            float ue[4] = {uu.x, uu.y, uu.z, uu.w};
            float rwv[4], kkv[4];
            float dpart = 0.f;
            #pragma unroll
            for (int e = 0; e < 4; ++e) {
                rwv[e] = f2tf(re[e] * __expf(cpe[e]));
                kkv[e] = f2tf(ke[e] * __expf(-ce[e]));
                dpart += re[e] * ue[e] * ke[e];
            }
            *(float4*)&sm[O_RW + t * 68 + k0] = make_float4(rwv[0], rwv[1], rwv[2], rwv[3]);
            *(float4*)&sm[O_KK + t * 76 + k0] = make_float4(kkv[0], kkv[1], kkv[2], kkv[3]);
            *(float4*)&g_rwi[base + f4 * 4]   = make_float4(rwv[0], rwv[1], rwv[2], rwv[3]);
            float dv = dpart;
            #pragma unroll
            for (int s = 1; s < 16; s <<= 1) dv += __shfl_xor_sync(0xffffffffu, dv, s, 16);
            if ((tid & 15) == 0) sm[O_DIAG + t] = dv;
        }
    }
    __syncthreads();

    const int jh = wid >> 3;
    const int widL = wid & 7;
    const int blk = (widL < 4) ? widL : 11 - widL;
    const int i0 = blk * 16;
    int ntmax = (i0 + 16 - jh * 64) >> 3;
    ntmax = ntmax < 0 ? 0 : (ntmax > 8 ? 8 : ntmax);

    float c1[8][4];
    #pragma unroll
    for (int nt = 0; nt < 8; ++nt)
        #pragma unroll
        for (int e = 0; e < 4; ++e) c1[nt][e] = 0.f;

    #pragma unroll
    for (int ks = 0; ks < 8; ++ks) {
        int k0 = ks * 8;
        const float* ar = &sm[O_RW + (i0 + ly) * 68 + k0 + lx];
        uint32_t a0 = FB(ar[0]), a1 = FB(ar[8 * 68]), a2 = FB(ar[4]), a3 = FB(ar[8 * 68 + 4]);
        #pragma unroll
        for (int nt = 0; nt < 8; ++nt) {
            if (nt < ntmax) {
                const float* br = &sm[O_KK + (jh * 64 + nt * 8 + ly) * 76 + k0 + lx];
                mma1688(c1[nt], a0, a1, a2, a3, FB(br[0]), FB(br[4]));
            }
        }
    }

    {
        const int i0k = (wid & 3) * 16, j0c = (wid >> 2) * 16;
        float c3[2][4];
        #pragma unroll
        for (int nt = 0; nt < 2; ++nt)
            #pragma unroll
            for (int e = 0; e < 4; ++e) c3[nt][e] = 0.f;
        #pragma unroll
        for (int ks = 0; ks < 16; ++ks) {
            int k0 = ks * 8;
            const float* ac = &sm[O_KK + (k0 + lx) * 76 + i0k + ly];
            uint32_t a0 = FB(ac[0]), a1 = FB(ac[8]), a2 = FB(ac[4 * 76]), a3 = FB(ac[4 * 76 + 8]);
            #pragma unroll
            for (int nt = 0; nt < 2; ++nt) {
                const float* br = &sm[O_V + (k0 + lx) * 72 + j0c + nt * 8 + ly];
                mma1688(c3[nt], a0, a1, a2, a3, FB(br[0]), FB(br[4 * 72]));
            }
        }
        int wb = bhn * (K_ * K_);
        int il = i0k + ly, ih = il + 8;
        float sl = sm[O_EWS + il], sh = sm[O_EWS + ih];
        #pragma unroll
        for (int nt = 0; nt < 2; ++nt) {
            int jb = j0c + nt * 8 + 2 * lx;
            *(float2*)&g_wkv[wb + il * 64 + jb] = make_float2(c3[nt][0] * sl, c3[nt][1] * sl);
            *(float2*)&g_wkv[wb + ih * 64 + jb] = make_float2(c3[nt][2] * sh, c3[nt][3] * sh);
        }
    }
    __syncthreads();

    float c2[8][4];
    #pragma unroll
    for (int nt = 0; nt < 8; ++nt)
        #pragma unroll
        for (int e = 0; e < 4; ++e) c2[nt][e] = 0.f;

    {
        const int il = i0 + ly, ih = il + 8;
        const int l1 = ly * 4 + (lx >> 1);
        const int l2 = l1 + 2;
        const bool odd = lx & 1;
        #pragma unroll
        for (int nt = 0; nt < 8; ++nt) {
            if (nt < ntmax) {
                int jc = jh * 64 + nt * 8;
                int jcg = jc + 2 * lx;
                float m0 = (jcg     < il) ? f2tf(c1[nt][0]) : 0.f;
                float m1 = (jcg + 1 < il) ? f2tf(c1[nt][1]) : 0.f;
                float m2 = (jcg     < ih) ? f2tf(c1[nt][2]) : 0.f;
                float m3 = (jcg + 1 < ih) ? f2tf(c1[nt][3]) : 0.f;
                float t00 = __shfl_sync(0xffffffffu, m0, l1);
                float t01 = __shfl_sync(0xffffffffu, m1, l1);
                float t20 = __shfl_sync(0xffffffffu, m0, l2);
                float t21 = __shfl_sync(0xffffffffu, m1, l2);
                float t10 = __shfl_sync(0xffffffffu, m2, l1);
                float t11 = __shfl_sync(0xffffffffu, m3, l1);
                float t30 = __shfl_sync(0xffffffffu, m2, l2);
                float t31 = __shfl_sync(0xffffffffu, m3, l2);
                uint32_t a0 = FB(odd ? t01 : t00);
                uint32_t a2 = FB(odd ? t21 : t20);
                uint32_t a1 = FB(odd ? t11 : t10);
                uint32_t a3 = FB(odd ? t31 : t30);
                #pragma unroll
                for (int no = 0; no < 8; ++no) {
                    const float* br = &sm[O_V + (jc + lx) * 72 + no * 8 + ly];
                    mma1688(c2[no], a0, a1, a2, a3, FB(br[0]), FB(br[4 * 72]));
                }
            }
        }
    }

    if (jh == 1 && ntmax > 0) {
        float* pb = &sm[O_RW + (blk - 4) * 1088];
        int jb = 2 * lx;
        #pragma unroll
        for (int nt = 0; nt < 8; ++nt) {
            *(float2*)&pb[ly * 68 + nt * 8 + jb]       = make_float2(c2[nt][0], c2[nt][1]);
            *(float2*)&pb[(ly + 8) * 68 + nt * 8 + jb] = make_float2(c2[nt][2], c2[nt][3]);
        }
    }
    __syncthreads();

    if (jh == 0) {
        const int il = i0 + ly, ih = il + 8;
        const float dgl = sm[O_DIAG + il], dgh = sm[O_DIAG + ih];
        const bool haveP = (blk >= 4);
        const float* pb = &sm[O_RW + (blk - 4) * 1088];
        #pragma unroll
        for (int nt = 0; nt < 8; ++nt) {
            int jb = nt * 8 + 2 * lx;
            float2 pl = make_float2(0.f, 0.f), ph = make_float2(0.f, 0.f);
            if (haveP) {
                pl = *(const float2*)&pb[ly * 68 + jb];
                ph = *(const float2*)&pb[(ly + 8) * 68 + jb];
            }
            float2 vl = *(const float2*)&sm[O_V + il * 72 + jb];
            float2 vh = *(const float2*)&sm[O_V + ih * 72 + jb];
            float o0 = c2[nt][0] + pl.x + dgl * vl.x;
            float o1 = c2[nt][1] + pl.y + dgl * vl.y;
            float o2 = c2[nt][2] + ph.x + dgh * vh.x;
            float o3 = c2[nt][3] + ph.y + dgh * vh.y;
            *(float2*)&out[base + il * 64 + jb] = make_float2(o0, o1);
            *(float2*)&out[base + ih * 64 + jb] = make_float2(o2, o3);
        }
    }
}

// ====== fused scan + inter-chunk contribution (v3: warp-autonomous, no barriers) ======
// grid: bh(64) x col-quarter(4) = 256 blocks, 256 threads.
// Warp w: out rows w*16..w*16+15 (all chunks), state slice 64x16 kept redundantly
// in registers in B-fragment layout. rw staged per-warp via cp.async double buffer.
#define FW_STRIDE 1088              // 16 x 68 floats per buffer
#define FUSED_FLOATS (16 * FW_STRIDE)   // 8 warps x 2 buffers
#define FUSED_BYTES  (FUSED_FLOATS * 4)

__global__ void __launch_bounds__(256, 2)
rwkv_scan_inter(const float* __restrict__ state0, float* __restrict__ out,
                float* __restrict__ outF)
{
    extern __shared__ float sm[];
    const int tid = threadIdx.x;
    const int wid = tid >> 5, lid = tid & 31;
    const int ly = lid >> 2, lx = lid & 3;
    const int bh = blockIdx.x >> 2;
    const int j0c = (blockIdx.x & 3) * 16;
    const int base_bh = bh * (T_ * K_);
    const int i0 = wid * 16;

    float* buf0 = &sm[wid * 2 * FW_STRIDE];
    float* buf1 = buf0 + FW_STRIDE;
    const uint32_t b0a = smem_u32(buf0);
    const uint32_t b1a = smem_u32(buf1);

    // lane's cp.async slots: f4 = lid + it*32 -> t = f4>>4 (0..15), k0 = (f4&15)*4
    int cp_t[8], cp_k[8];
    #pragma unroll
    for (int it = 0; it < 8; ++it) {
        int f4 = lid + it * 32;
        cp_t[it] = f4 >> 4;
        cp_k[it] = (f4 & 15) * 4;
    }

    // state slice in registers, B-fragment layout:
    // sreg[ks][nt][e] = state[ks*8 + lx + e*4][j0c + nt*8 + ly]
    float sreg[8][2][2];
    #pragma unroll
    for (int ks = 0; ks < 8; ++ks)
        #pragma unroll
        for (int nt = 0; nt < 2; ++nt)
            #pragma unroll
            for (int e = 0; e < 2; ++e)
                sreg[ks][nt][e] = state0[bh * (K_ * K_) + (ks * 8 + lx + e * 4) * 64 + j0c + nt * 8 + ly];

    // preload chunk 0 rw tile into buf0
    {
        const float* src = g_rwi + base_bh + i0 * 64;
        #pragma unroll
        for (int it = 0; it < 8; ++it)
            cp_async16(b0a + (cp_t[it] * 68 + cp_k[it]) * 4, src + cp_t[it] * 64 + cp_k[it]);
        cp_commit();
        cp_wait0();
        __syncwarp();
    }

    for (int n = 0; n < N_; ++n) {
        const float* cbuf = (n & 1) ? buf1 : buf0;
        const uint32_t nbuf = (n & 1) ? b0a : b1a;

        // prefetch next chunk's rw tile (async into other buffer)
        if (n < 15) {
            const float* src = g_rwi + base_bh + (n + 1) * (CH_ * K_) + i0 * 64;
            #pragma unroll
            for (int it = 0; it < 8; ++it)
                cp_async16(nbuf + (cp_t[it] * 68 + cp_k[it]) * 4, src + cp_t[it] * 64 + cp_k[it]);
            cp_commit();
        }

        // prefetch wkv (B-fragment layout) + ews for this chunk
        const int cb = bh * N_ + n;
        const float* wkvp = g_wkv + cb * (K_ * K_);
        const float* ewsp = g_wse + cb * K_;
        float wkvr[8][2][2], ewsr[8][2];
        #pragma unroll
        for (int ks = 0; ks < 8; ++ks) {
            #pragma unroll
            for (int e = 0; e < 2; ++e) {
                int kk = ks * 8 + lx + e * 4;
                ewsr[ks][e] = __ldg(&ewsp[kk]);
                #pragma unroll
                for (int nt = 0; nt < 2; ++nt)
                    wkvr[ks][nt][e] = __ldg(&wkvp[kk * 64 + j0c + nt * 8 + ly]);
            }
        }

        // prefetch out tile (RMW load overlaps MMAs)
        float* ob = out + base_bh + n * (CH_ * K_);
        const int il = i0 + ly, ih = il + 8;
        float2 o_l[2], o_h[2];
        #pragma unroll
        for (int nt = 0; nt < 2; ++nt) {
            int jb = j0c + nt * 8 + 2 * lx;
            o_l[nt] = *(const float2*)&ob[il * 64 + jb];
            o_h[nt] = *(const float2*)&ob[ih * 64 + jb];
        }

        // MMAs: 16x16 tile += rw(16x64) @ state(64x16); B from registers (tf32-rounded)
        float c[2][4];
        #pragma unroll
        for (int nt = 0; nt < 2; ++nt)
            #pragma unroll
            for (int e = 0; e < 4; ++e) c[nt][e] = 0.f;

        #pragma unroll
        for (int ks = 0; ks < 8; ++ks) {
            const float* ar = &cbuf[ly * 68 + ks * 8 + lx];
            uint32_t a0 = FB(ar[0]), a1 = FB(ar[8 * 68]), a2 = FB(ar[4]), a3 = FB(ar[8 * 68 + 4]);
            #pragma unroll
            for (int nt = 0; nt < 2; ++nt) {
                uint32_t bb0 = FB(f2tf(sreg[ks][nt][0]));
                uint32_t bb1 = FB(f2tf(sreg[ks][nt][1]));
                mma1688(c[nt], a0, a1, a2, a3, bb0, bb1);
            }
        }

        // out RMW store
        #pragma unroll
        for (int nt = 0; nt < 2; ++nt) {
            int jb = j0c + nt * 8 + 2 * lx;
            o_l[nt].x += c[nt][0]; o_l[nt].y += c[nt][1];
            o_h[nt].x += c[nt][2]; o_h[nt].y += c[nt][3];
            *(float2*)&ob[il * 64 + jb] = o_l[nt];
            *(float2*)&ob[ih * 64 + jb] = o_h[nt];
        }

        // state update (exact fp32)
        #pragma unroll
        for (int ks = 0; ks < 8; ++ks)
            #pragma unroll
            for (int nt = 0; nt < 2; ++nt)
                #pragma unroll
                for (int e = 0; e < 2; ++e)
                    sreg[ks][nt][e] = fmaf(sreg[ks][nt][e], ewsr[ks][e], wkvr[ks][nt][e]);

        if (n < 15) { cp_wait0(); }
        __syncwarp();
    }

    // final state: warp 0 holds the full (redundant) 64x16 slice — write it out
    if (wid == 0) {
        #pragma unroll
        for (int ks = 0; ks < 8; ++ks)
            #pragma unroll
            for (int nt = 0; nt < 2; ++nt)
                #pragma unroll
                for (int e = 0; e < 2; ++e)
                    outF[bh * (K_ * K_) + (ks * 8 + lx + e * 4) * 64 + j0c + nt * 8 + ly] =
                        sreg[ks][nt][e];
    }
}

extern "C" void kernel_launch(void* const* d_in, const int* in_sizes, int n_in,
                              void* d_out, int out_size)
{
    (void)in_sizes; (void)n_in; (void)out_size;
    const float* r  = (const float*)d_in[0];
    const float* k  = (const float*)d_in[1];
    const float* v  = (const float*)d_in[2];
    const float* w  = (const float*)d_in[3];
    const float* u  = (const float*)d_in[4];
    const float* s0 = (const float*)d_in[5];
    float* out  = (float*)d_out;
    float* outF = out + OUT_ELEMS;

    cudaFuncSetAttribute(rwkv_phase1, cudaFuncAttributeMaxDynamicSharedMemorySize, SMEM1_BYTES);
    cudaFuncSetAttribute(rwkv_scan_inter, cudaFuncAttributeMaxDynamicSharedMemorySize, FUSED_BYTES);

    rwkv_phase1<<<BH_ * N_, 512, SMEM1_BYTES>>>(r, k, v, w, u, out);
    rwkv_scan_inter<<<BH_ * 4, 256, FUSED_BYTES>>>(s0, out, outF);
}